// round 3
// baseline (speedup 1.0000x reference)
#include <cuda_runtime.h>
#include <math.h>

// Problem constants
#define B   16
#define C   256     // Cin == Cout
#define Hh  64
#define Ww  64
#define E   8
#define HW  (Hh * Ww)          // 4096
#define WN  (C * C * 9)        // per-expert weight elements = 589824

// Scratch (allocation-free rule: __device__ globals)
__device__ float g_pooled[B * C];
__device__ float g_routing[B * E];
__device__ float g_aggb[B * C];
__device__ float g_aggw[B * WN];   // [b][co][ci][3][3], 37.75 MB

// ---------------------------------------------------------------------------
// Kernel 1: global average pool.  One block per (b, ci); 256 threads reduce
// 4096 contiguous floats (coalesced).
// ---------------------------------------------------------------------------
__global__ void pool_kernel(const float* __restrict__ x) {
    int blk = blockIdx.x;                       // b*C + ci
    const float* p = x + (size_t)blk * HW;
    float s = 0.f;
    for (int i = threadIdx.x; i < HW; i += 256) s += p[i];
    #pragma unroll
    for (int o = 16; o; o >>= 1) s += __shfl_xor_sync(0xFFFFFFFFu, s, o);
    __shared__ float wsum[8];
    if ((threadIdx.x & 31) == 0) wsum[threadIdx.x >> 5] = s;
    __syncthreads();
    if (threadIdx.x == 0) {
        float t = 0.f;
        #pragma unroll
        for (int w = 0; w < 8; w++) t += wsum[w];
        g_pooled[blk] = t * (1.0f / HW);
    }
}

// ---------------------------------------------------------------------------
// Kernel 2: routing (sigmoid(pooled @ rw^T + rb)) and aggregated bias.
// Single block of 256 threads.
// ---------------------------------------------------------------------------
__global__ void routing_kernel(const float* __restrict__ rw,
                               const float* __restrict__ rb,
                               const float* __restrict__ bias) {
    __shared__ float rt[B * E];
    int t = threadIdx.x;
    if (t < B * E) {
        int b = t / E, e = t % E;
        float acc = rb[e];
        const float* pp = g_pooled + b * C;
        const float* ww = rw + e * C;
        for (int c = 0; c < C; c++) acc += pp[c] * ww[c];
        float r = 1.0f / (1.0f + expf(-acc));
        rt[t] = r;
        g_routing[t] = r;
    }
    __syncthreads();
    // agg_b[b][co] = sum_e rt[b][e] * bias[e][co]; thread t owns co = t
    int co = t;
    float be[E];
    #pragma unroll
    for (int e = 0; e < E; e++) be[e] = bias[e * C + co];
    #pragma unroll
    for (int b = 0; b < B; b++) {
        float a = 0.f;
        #pragma unroll
        for (int e = 0; e < E; e++) a += rt[b * E + e] * be[e];
        g_aggb[b * C + co] = a;
    }
}

// ---------------------------------------------------------------------------
// Kernel 3: weight aggregation.  Each thread reads one weight element from all
// 8 experts once and emits the 16 per-sample mixtures (reads 19MB, writes 38MB).
// ---------------------------------------------------------------------------
__global__ void aggw_kernel(const float* __restrict__ weight) {
    __shared__ float rt[B * E];
    if (threadIdx.x < B * E) rt[threadIdx.x] = g_routing[threadIdx.x];
    __syncthreads();
    int i = blockIdx.x * blockDim.x + threadIdx.x;
    if (i >= WN) return;
    float w[E];
    #pragma unroll
    for (int e = 0; e < E; e++) w[e] = weight[(size_t)e * WN + i];
    #pragma unroll
    for (int b = 0; b < B; b++) {
        float a = 0.f;
        #pragma unroll
        for (int e = 0; e < E; e++) a += rt[b * E + e] * w[e];
        g_aggw[(size_t)b * WN + i] = a;
    }
}

// ---------------------------------------------------------------------------
// Kernel 4: direct conv 3x3, pad 1, per-sample aggregated weights.
// Block tile: 64 Cout x (4 rows x 64 cols) pixels.  256 threads, each computes
// an 8x8 (cout x pixel) register tile.  K-loop over Cin in chunks of KC=4.
// Weight smem reads are warp-uniform (broadcast); x smem row stride 70 keeps
// bank conflicts <= 2-way.
// ---------------------------------------------------------------------------
#define KC      4
#define XS_W    70
#define CO_TILE 64

__global__ __launch_bounds__(256, 2)
void conv_kernel(const float* __restrict__ x, float* __restrict__ out) {
    __shared__ float xs[KC][6][XS_W];        // rows y0-1..y0+4, cols -1..64
    __shared__ float ws[CO_TILE][KC * 9];

    int b   = blockIdx.z;
    int co0 = blockIdx.y * CO_TILE;
    int y0  = blockIdx.x * 4;
    int tid = threadIdx.x;
    int tm  = tid >> 5;                // 0..7 : cout group of 8
    int tn  = tid & 31;                // 0..31: pixel group of 8
    int py  = tn >> 3;                 // row within 4-row tile
    int px0 = (tn & 7) << 3;           // col start (8 consecutive)

    float acc[8][8];
    #pragma unroll
    for (int m = 0; m < 8; m++)
        #pragma unroll
        for (int c = 0; c < 8; c++) acc[m][c] = 0.f;

    const float* xb = x + (size_t)b * C * HW;

    for (int ci0 = 0; ci0 < C; ci0 += KC) {
        // ---- stage x tile (KC ch x 6 rows x 66 cols, zero-padded halo) ----
        for (int idx = tid; idx < KC * 6 * 66; idx += 256) {
            int cil = idx / (6 * 66);
            int rem = idx % (6 * 66);
            int row = rem / 66;
            int col = rem % 66;
            int gy  = y0 + row - 1;
            int gx  = col - 1;
            float v = 0.f;
            if (gy >= 0 && gy < Hh && gx >= 0 && gx < Ww)
                v = xb[(ci0 + cil) * HW + gy * Ww + gx];
            xs[cil][row][col] = v;
        }
        // ---- stage weights: 64 co x (KC*9) contiguous-per-co ----
        {
            int co = tid >> 2;                 // 0..63
            int j0 = (tid & 3) * 9;            // 0,9,18,27
            const float* wp = g_aggw + ((size_t)(b * C + co0 + co) * C + ci0) * 9 + j0;
            float* wd = &ws[co][j0];
            #pragma unroll
            for (int j = 0; j < 9; j++) wd[j] = wp[j];
        }
        __syncthreads();

        // ---- compute ----
        #pragma unroll
        for (int cil = 0; cil < KC; cil++) {
            #pragma unroll
            for (int r = 0; r < 3; r++) {
                float xv[10];
                #pragma unroll
                for (int k = 0; k < 10; k++) xv[k] = xs[cil][py + r][px0 + k];
                #pragma unroll
                for (int s = 0; s < 3; s++) {
                    float wv[8];
                    #pragma unroll
                    for (int m = 0; m < 8; m++)
                        wv[m] = ws[tm * 8 + m][cil * 9 + r * 3 + s];
                    #pragma unroll
                    for (int m = 0; m < 8; m++)
                        #pragma unroll
                        for (int c = 0; c < 8; c++)
                            acc[m][c] += wv[m] * xv[s + c];
                }
            }
        }
        __syncthreads();
    }

    // ---- epilogue: add aggregated bias, store 8 consecutive floats/row ----
    #pragma unroll
    for (int m = 0; m < 8; m++) {
        int co = co0 + tm * 8 + m;
        float bb = g_aggb[b * C + co];
        float* op = out + ((size_t)(b * C + co) * Hh + (y0 + py)) * Ww + px0;
        #pragma unroll
        for (int c = 0; c < 8; c++) op[c] = acc[m][c] + bb;
    }
}

// ---------------------------------------------------------------------------
extern "C" void kernel_launch(void* const* d_in, const int* in_sizes, int n_in,
                              void* d_out, int out_size) {
    (void)in_sizes; (void)n_in; (void)out_size;
    const float* x      = (const float*)d_in[0];
    const float* weight = (const float*)d_in[1];
    const float* bias   = (const float*)d_in[2];
    const float* rw     = (const float*)d_in[3];
    const float* rb     = (const float*)d_in[4];
    float* out          = (float*)d_out;

    pool_kernel<<<B * C, 256>>>(x);
    routing_kernel<<<1, 256>>>(rw, rb, bias);
    aggw_kernel<<<(WN + 255) / 256, 256>>>(weight);
    conv_kernel<<<dim3(Hh / 4, C / CO_TILE, B), 256>>>(x, out);
}

// round 4
// speedup vs baseline: 1.0039x; 1.0039x over previous
#include <cuda_runtime.h>
#include <math.h>

// Problem constants
#define B   16
#define C   256     // Cin == Cout
#define Hh  64
#define Ww  64
#define E   8
#define HW  (Hh * Ww)          // 4096
#define WN  (C * C * 9)        // per-expert weight elements = 589824

// Scratch (allocation-free rule: __device__ globals)
__device__ float g_pooled[B * C];
__device__ float g_routing[B * E];
__device__ float g_aggb[B * C];
__device__ float g_aggw[B * WN];   // [b][co][ci][3][3], 37.75 MB

// ---- packed f32x2 helpers (sm_100a) --------------------------------------
__device__ __forceinline__ unsigned long long pk2(float lo, float hi) {
    unsigned long long r;
    asm("mov.b64 %0, {%1, %2};" : "=l"(r) : "f"(lo), "f"(hi));
    return r;
}
__device__ __forceinline__ void fma2(unsigned long long& d,
                                     unsigned long long a,
                                     unsigned long long b) {
    asm("fma.rn.f32x2 %0, %1, %2, %0;" : "+l"(d) : "l"(a), "l"(b));
}
__device__ __forceinline__ void upk2(float& lo, float& hi, unsigned long long v) {
    asm("mov.b64 {%0, %1}, %2;" : "=f"(lo), "=f"(hi) : "l"(v));
}

// ---------------------------------------------------------------------------
// Kernel 1: global average pool.  One block per (b, ci).
// ---------------------------------------------------------------------------
__global__ void pool_kernel(const float* __restrict__ x) {
    int blk = blockIdx.x;                       // b*C + ci
    const float* p = x + (size_t)blk * HW;
    float s = 0.f;
    for (int i = threadIdx.x; i < HW; i += 256) s += p[i];
    #pragma unroll
    for (int o = 16; o; o >>= 1) s += __shfl_xor_sync(0xFFFFFFFFu, s, o);
    __shared__ float wsum[8];
    if ((threadIdx.x & 31) == 0) wsum[threadIdx.x >> 5] = s;
    __syncthreads();
    if (threadIdx.x == 0) {
        float t = 0.f;
        #pragma unroll
        for (int w = 0; w < 8; w++) t += wsum[w];
        g_pooled[blk] = t * (1.0f / HW);
    }
}

// ---------------------------------------------------------------------------
// Kernel 2: routing (sigmoid) + aggregated bias.  One block.
// ---------------------------------------------------------------------------
__global__ void routing_kernel(const float* __restrict__ rw,
                               const float* __restrict__ rb,
                               const float* __restrict__ bias) {
    __shared__ float rt[B * E];
    int t = threadIdx.x;
    if (t < B * E) {
        int b = t / E, e = t % E;
        float acc = rb[e];
        const float* pp = g_pooled + b * C;
        const float* ww = rw + e * C;
        for (int c = 0; c < C; c++) acc += pp[c] * ww[c];
        float r = 1.0f / (1.0f + expf(-acc));
        rt[t] = r;
        g_routing[t] = r;
    }
    __syncthreads();
    int co = t;
    float be[E];
    #pragma unroll
    for (int e = 0; e < E; e++) be[e] = bias[e * C + co];
    #pragma unroll
    for (int b = 0; b < B; b++) {
        float a = 0.f;
        #pragma unroll
        for (int e = 0; e < E; e++) a += rt[b * E + e] * be[e];
        g_aggb[b * C + co] = a;
    }
}

// ---------------------------------------------------------------------------
// Kernel 3: weight aggregation -> g_aggw.
// ---------------------------------------------------------------------------
__global__ void aggw_kernel(const float* __restrict__ weight) {
    __shared__ float rt[B * E];
    if (threadIdx.x < B * E) rt[threadIdx.x] = g_routing[threadIdx.x];
    __syncthreads();
    int i = blockIdx.x * blockDim.x + threadIdx.x;
    if (i >= WN) return;
    float w[E];
    #pragma unroll
    for (int e = 0; e < E; e++) w[e] = weight[(size_t)e * WN + i];
    #pragma unroll
    for (int b = 0; b < B; b++) {
        float a = 0.f;
        #pragma unroll
        for (int e = 0; e < E; e++) a += rt[b * E + e] * w[e];
        g_aggw[(size_t)b * WN + i] = a;
    }
}

// ---------------------------------------------------------------------------
// Kernel 4: direct conv 3x3, pad 1, packed-f32x2 math path.
// Block tile: 64 Cout x (4 rows x 64 cols).  256 threads, each owns an
// 8 (cout) x 8 (cols, as 4 f32x2 pairs) register tile.
// Weights staged pre-splatted (w,w) -> one LDS.64 per use, warp-uniform.
// x tile row stride 72 (16B-aligned rows) -> vector LDS for the 10-wide window.
// ---------------------------------------------------------------------------
#define KC      4
#define XS_W    72
#define CO_TILE 64

__global__ __launch_bounds__(256, 2)
void conv_kernel(const float* __restrict__ x, float* __restrict__ out) {
    __shared__ __align__(16) float xs[KC][6][XS_W];   // rows y0-1..y0+4, cols -1..64
    __shared__ __align__(8)  float2 ws2[CO_TILE][KC * 9];  // (w,w) splats

    int b   = blockIdx.z;
    int co0 = blockIdx.y * CO_TILE;
    int y0  = blockIdx.x * 4;
    int tid = threadIdx.x;
    int tm  = tid >> 5;                // 0..7 : cout group of 8
    int tn  = tid & 31;                // 0..31: pixel group
    int py  = tn >> 3;                 // row within 4-row tile
    int px0 = (tn & 7) << 3;           // col start (8 consecutive), 32B aligned

    unsigned long long acc[8][4];
    #pragma unroll
    for (int m = 0; m < 8; m++)
        #pragma unroll
        for (int j = 0; j < 4; j++) acc[m][j] = 0ull;

    const float* xb = x + (size_t)b * C * HW;

    for (int ci0 = 0; ci0 < C; ci0 += KC) {
        // ---- stage x tile (KC ch x 6 rows x 66 cols, zero-padded halo) ----
        for (int idx = tid; idx < KC * 6 * 66; idx += 256) {
            int cil = idx / (6 * 66);
            int rem = idx % (6 * 66);
            int row = rem / 66;
            int col = rem % 66;
            int gy  = y0 + row - 1;
            int gx  = col - 1;
            float v = 0.f;
            if (gy >= 0 && gy < Hh && gx >= 0 && gx < Ww)
                v = xb[(ci0 + cil) * HW + gy * Ww + gx];
            xs[cil][row][col] = v;
        }
        // ---- stage weights pre-splatted: 64 co x (KC*9) float2 ----
        {
            int co = tid >> 2;                 // 0..63
            int j0 = (tid & 3) * 9;            // 0,9,18,27
            const float* wp = g_aggw + ((size_t)(b * C + co0 + co) * C + ci0) * 9 + j0;
            float2* wd = &ws2[co][j0];
            #pragma unroll
            for (int j = 0; j < 9; j++) { float w = wp[j]; wd[j] = make_float2(w, w); }
        }
        __syncthreads();

        // ---- compute ----
        #pragma unroll
        for (int cil = 0; cil < KC; cil++) {
            #pragma unroll
            for (int r = 0; r < 3; r++) {
                const float* row = &xs[cil][py + r][px0];
                float4 va = *reinterpret_cast<const float4*>(row);
                float4 vb = *reinterpret_cast<const float4*>(row + 4);
                float2 vc = *reinterpret_cast<const float2*>(row + 8);
                // 9 shifted pairs p[k] = (x[k], x[k+1])
                unsigned long long p[9];
                p[0] = pk2(va.x, va.y);
                p[1] = pk2(va.y, va.z);
                p[2] = pk2(va.z, va.w);
                p[3] = pk2(va.w, vb.x);
                p[4] = pk2(vb.x, vb.y);
                p[5] = pk2(vb.y, vb.z);
                p[6] = pk2(vb.z, vb.w);
                p[7] = pk2(vb.w, vc.x);
                p[8] = pk2(vc.x, vc.y);

                #pragma unroll
                for (int s = 0; s < 3; s++) {
                    #pragma unroll
                    for (int m = 0; m < 8; m++) {
                        unsigned long long w2 =
                            *reinterpret_cast<const unsigned long long*>(
                                &ws2[tm * 8 + m][cil * 9 + r * 3 + s]);
                        fma2(acc[m][0], w2, p[s + 0]);
                        fma2(acc[m][1], w2, p[s + 2]);
                        fma2(acc[m][2], w2, p[s + 4]);
                        fma2(acc[m][3], w2, p[s + 6]);
                    }
                }
            }
        }
        __syncthreads();
    }

    // ---- epilogue: add aggregated bias, vector stores ----
    #pragma unroll
    for (int m = 0; m < 8; m++) {
        int co = co0 + tm * 8 + m;
        float bb = g_aggb[b * C + co];
        float* op = out + ((size_t)(b * C + co) * Hh + (y0 + py)) * Ww + px0;
        float4 o0, o1;
        float lo, hi;
        upk2(lo, hi, acc[m][0]); o0.x = lo + bb; o0.y = hi + bb;
        upk2(lo, hi, acc[m][1]); o0.z = lo + bb; o0.w = hi + bb;
        upk2(lo, hi, acc[m][2]); o1.x = lo + bb; o1.y = hi + bb;
        upk2(lo, hi, acc[m][3]); o1.z = lo + bb; o1.w = hi + bb;
        *reinterpret_cast<float4*>(op)     = o0;
        *reinterpret_cast<float4*>(op + 4) = o1;
    }
}

// ---------------------------------------------------------------------------
extern "C" void kernel_launch(void* const* d_in, const int* in_sizes, int n_in,
                              void* d_out, int out_size) {
    (void)in_sizes; (void)n_in; (void)out_size;
    const float* x      = (const float*)d_in[0];
    const float* weight = (const float*)d_in[1];
    const float* bias   = (const float*)d_in[2];
    const float* rw     = (const float*)d_in[3];
    const float* rb     = (const float*)d_in[4];
    float* out          = (float*)d_out;

    pool_kernel<<<B * C, 256>>>(x);
    routing_kernel<<<1, 256>>>(rw, rb, bias);
    aggw_kernel<<<(WN + 255) / 256, 256>>>(weight);
    conv_kernel<<<dim3(Hh / 4, C / CO_TILE, B), 256>>>(x, out);
}

// round 5
// speedup vs baseline: 1.9644x; 1.9567x over previous
#include <cuda_runtime.h>
#include <math.h>
#include <stdint.h>

// Problem constants
#define B   16
#define C   256     // Cin == Cout
#define Hh  64
#define Ww  64
#define E   8
#define HW  (Hh * Ww)          // 4096
#define WN  (C * C * 9)        // per-expert weight elements = 589824

// Scratch (allocation-free rule: __device__ globals)
__device__ float g_pooled[B * C];
__device__ float g_routing[B * E];
__device__ float g_aggb[B * C];
__device__ float g_aggw[B * WN];   // [b][co][ci][3][3], tf32-rounded floats

// ---- tf32 helpers ---------------------------------------------------------
__device__ __forceinline__ uint32_t tf32r(float f) {
    uint32_t u;
    asm("cvt.rna.tf32.f32 %0, %1;" : "=r"(u) : "f"(f));
    return u;
}

// ---------------------------------------------------------------------------
// Kernel 1: global average pool.  One block per (b, ci).
// ---------------------------------------------------------------------------
__global__ void pool_kernel(const float* __restrict__ x) {
    int blk = blockIdx.x;                       // b*C + ci
    const float* p = x + (size_t)blk * HW;
    float s = 0.f;
    for (int i = threadIdx.x; i < HW; i += 256) s += p[i];
    #pragma unroll
    for (int o = 16; o; o >>= 1) s += __shfl_xor_sync(0xFFFFFFFFu, s, o);
    __shared__ float wsum[8];
    if ((threadIdx.x & 31) == 0) wsum[threadIdx.x >> 5] = s;
    __syncthreads();
    if (threadIdx.x == 0) {
        float t = 0.f;
        #pragma unroll
        for (int w = 0; w < 8; w++) t += wsum[w];
        g_pooled[blk] = t * (1.0f / HW);
    }
}

// ---------------------------------------------------------------------------
// Kernel 2: routing (sigmoid) + aggregated bias.  One block.
// ---------------------------------------------------------------------------
__global__ void routing_kernel(const float* __restrict__ rw,
                               const float* __restrict__ rb,
                               const float* __restrict__ bias) {
    __shared__ float rt[B * E];
    int t = threadIdx.x;
    if (t < B * E) {
        int b = t / E, e = t % E;
        float acc = rb[e];
        const float* pp = g_pooled + b * C;
        const float* ww = rw + e * C;
        for (int c = 0; c < C; c++) acc += pp[c] * ww[c];
        float r = 1.0f / (1.0f + expf(-acc));
        rt[t] = r;
        g_routing[t] = r;
    }
    __syncthreads();
    int co = t;
    float be[E];
    #pragma unroll
    for (int e = 0; e < E; e++) be[e] = bias[e * C + co];
    #pragma unroll
    for (int b = 0; b < B; b++) {
        float a = 0.f;
        #pragma unroll
        for (int e = 0; e < E; e++) a += rt[b * E + e] * be[e];
        g_aggb[b * C + co] = a;
    }
}

// ---------------------------------------------------------------------------
// Kernel 3: weight aggregation -> g_aggw (tf32-rounded, f32 aggregation math).
// ---------------------------------------------------------------------------
__global__ void aggw_kernel(const float* __restrict__ weight) {
    __shared__ float rt[B * E];
    if (threadIdx.x < B * E) rt[threadIdx.x] = g_routing[threadIdx.x];
    __syncthreads();
    int i = blockIdx.x * blockDim.x + threadIdx.x;
    if (i >= WN) return;
    float w[E];
    #pragma unroll
    for (int e = 0; e < E; e++) w[e] = weight[(size_t)e * WN + i];
    #pragma unroll
    for (int b = 0; b < B; b++) {
        float a = 0.f;
        #pragma unroll
        for (int e = 0; e < E; e++) a += rt[b * E + e] * w[e];
        g_aggw[(size_t)b * WN + i] = __uint_as_float(tf32r(a));
    }
}

// ---------------------------------------------------------------------------
// Kernel 4: tf32 tensor-core implicit-GEMM conv (3x3, pad 1).
//
// GEMM view: M = 64 couts, N = 64 pixels (one output row y), K = Cin*9 = 2304.
// K staged in chunks of 72 (8 channels x 9 taps); 9 m16n8k8 MMA k-steps/stage.
// 128 threads = 4 warps; warp w owns pixels [w*16, w*16+16), all 64 couts:
// 4 m-tiles x 2 n-tiles = 8 MMAs per k-step per warp.
//
// ws[64][76]: stride 76 => A-fragment LDS conflict-free (row*12+col covers all
// 32 banks).  xs[8][3][68]: shifted-window B reads, offsets precomputed once.
// ---------------------------------------------------------------------------
#define XPAD   68
#define KCH    8
#define WSP    76

__global__ __launch_bounds__(128, 4)
void conv_mma_kernel(const float* __restrict__ x, float* __restrict__ out) {
    __shared__ float xs[KCH * 3 * XPAD];   // [cl][r][col], col = gx+1
    __shared__ float ws[64 * WSP];         // [co][k within stage]

    const int b    = blockIdx.z;
    const int co0  = blockIdx.y * 64;
    const int y    = blockIdx.x;           // output row 0..63
    const int tid  = threadIdx.x;
    const int wrp  = tid >> 5;
    const int lane = tid & 31;
    const int g    = lane >> 2;            // 0..7
    const int tg   = lane & 3;             // 0..3
    const int px   = wrp * 16;             // warp pixel base

    float acc[4][2][4];
    #pragma unroll
    for (int i = 0; i < 4; i++)
        #pragma unroll
        for (int j = 0; j < 2; j++)
            #pragma unroll
            for (int c = 0; c < 4; c++) acc[i][j][c] = 0.f;

    // Precompute B smem offsets (floats) for 9 k-steps x 2 halves, n-tile 0.
    // kk = step*8 + tg + 4*h ; cl = kk/9 ; r = (kk%9)/3 ; s = kk%3
    int boff[9][2];
    #pragma unroll
    for (int step = 0; step < 9; step++) {
        #pragma unroll
        for (int h = 0; h < 2; h++) {
            int kk = step * 8 + tg + 4 * h;
            int cl = kk / 9;
            int j9 = kk - cl * 9;
            int r  = j9 / 3;
            int s  = j9 - r * 3;
            boff[step][h] = cl * (3 * XPAD) + r * XPAD + (px + g + s);
        }
    }

    const uint32_t* xsu = reinterpret_cast<const uint32_t*>(xs);
    const uint32_t* wsu = reinterpret_cast<const uint32_t*>(ws);

    for (int ci0 = 0; ci0 < C; ci0 += KCH) {
        // ---- stage x tile: 8 ch x 3 rows x 66 cols, tf32-rounded ----
        for (int idx = tid; idx < KCH * 3 * 66; idx += 128) {
            int cl  = idx / 198;
            int rem = idx - cl * 198;
            int r   = rem / 66;
            int col = rem - r * 66;
            int gy  = y + r - 1;
            int gx  = col - 1;
            float v = 0.f;
            if (gy >= 0 && gy < Hh && gx >= 0 && gx < Ww)
                v = x[(((size_t)b * C + ci0 + cl) * Hh + gy) * Ww + gx];
            xs[cl * (3 * XPAD) + r * XPAD + col] = __uint_as_float(tf32r(v));
        }
        // ---- stage weights: 64 co x 72 k (contiguous, float4) ----
        {
            int co   = tid >> 1;               // 0..63
            int half = tid & 1;                // 0,1 -> 36 floats each
            const float4* wp = reinterpret_cast<const float4*>(
                g_aggw + ((size_t)(b * C + co0 + co) * C + ci0) * 9 + half * 36);
            float4* wd = reinterpret_cast<float4*>(ws + co * WSP + half * 36);
            #pragma unroll
            for (int q = 0; q < 9; q++) wd[q] = wp[q];
        }
        __syncthreads();

        // ---- 9 MMA k-steps over this 72-wide K chunk ----
        #pragma unroll
        for (int step = 0; step < 9; step++) {
            const int kc = step * 8 + tg;
            uint32_t a[4][4];
            #pragma unroll
            for (int i = 0; i < 4; i++) {
                int r0 = (i * 16 + g) * WSP;
                int r1 = r0 + 8 * WSP;
                a[i][0] = wsu[r0 + kc];
                a[i][1] = wsu[r1 + kc];
                a[i][2] = wsu[r0 + kc + 4];
                a[i][3] = wsu[r1 + kc + 4];
            }
            #pragma unroll
            for (int j = 0; j < 2; j++) {
                uint32_t b0 = xsu[boff[step][0] + j * 8];
                uint32_t b1 = xsu[boff[step][1] + j * 8];
                #pragma unroll
                for (int i = 0; i < 4; i++) {
                    asm volatile(
                        "mma.sync.aligned.m16n8k8.row.col.f32.tf32.tf32.f32 "
                        "{%0,%1,%2,%3}, {%4,%5,%6,%7}, {%8,%9}, {%0,%1,%2,%3};"
                        : "+f"(acc[i][j][0]), "+f"(acc[i][j][1]),
                          "+f"(acc[i][j][2]), "+f"(acc[i][j][3])
                        : "r"(a[i][0]), "r"(a[i][1]), "r"(a[i][2]), "r"(a[i][3]),
                          "r"(b0), "r"(b1));
                }
            }
        }
        __syncthreads();
    }

    // ---- epilogue: bias + float2 stores ----
    #pragma unroll
    for (int i = 0; i < 4; i++) {
        int co_a = co0 + i * 16 + g;
        int co_b = co_a + 8;
        float bba = g_aggb[b * C + co_a];
        float bbb = g_aggb[b * C + co_b];
        #pragma unroll
        for (int j = 0; j < 2; j++) {
            int col = px + j * 8 + 2 * tg;
            float* pa = out + (((size_t)b * C + co_a) * Hh + y) * Ww + col;
            float* pb = out + (((size_t)b * C + co_b) * Hh + y) * Ww + col;
            *reinterpret_cast<float2*>(pa) =
                make_float2(acc[i][j][0] + bba, acc[i][j][1] + bba);
            *reinterpret_cast<float2*>(pb) =
                make_float2(acc[i][j][2] + bbb, acc[i][j][3] + bbb);
        }
    }
}

// ---------------------------------------------------------------------------
extern "C" void kernel_launch(void* const* d_in, const int* in_sizes, int n_in,
                              void* d_out, int out_size) {
    (void)in_sizes; (void)n_in; (void)out_size;
    const float* x      = (const float*)d_in[0];
    const float* weight = (const float*)d_in[1];
    const float* bias   = (const float*)d_in[2];
    const float* rw     = (const float*)d_in[3];
    const float* rb     = (const float*)d_in[4];
    float* out          = (float*)d_out;

    pool_kernel<<<B * C, 256>>>(x);
    routing_kernel<<<1, 256>>>(rw, rb, bias);
    aggw_kernel<<<(WN + 255) / 256, 256>>>(weight);
    conv_mma_kernel<<<dim3(Hh, C / 64, B), 128>>>(x, out);
}

// round 6
// speedup vs baseline: 2.2261x; 1.1332x over previous
#include <cuda_runtime.h>
#include <math.h>
#include <stdint.h>

// Problem constants
#define B   16
#define C   256     // Cin == Cout
#define Hh  64
#define Ww  64
#define E   8
#define HW  (Hh * Ww)          // 4096
#define WN  (C * C * 9)        // per-expert weight elements = 589824

// Scratch (allocation-free rule: __device__ globals)
__device__ float g_pooled[B * C];
__device__ float g_routing[B * E];
__device__ float g_aggb[B * C];
__device__ float g_aggw[B * WN];   // [b][co][ci][3][3], tf32-rounded floats

// ---- tf32 helpers ---------------------------------------------------------
__device__ __forceinline__ uint32_t tf32r(float f) {
    uint32_t u;
    asm("cvt.rna.tf32.f32 %0, %1;" : "=r"(u) : "f"(f));
    return u;
}

// ---------------------------------------------------------------------------
// Kernel 1: global average pool.  One block per (b, ci).
// ---------------------------------------------------------------------------
__global__ void pool_kernel(const float* __restrict__ x) {
    int blk = blockIdx.x;                       // b*C + ci
    const float* p = x + (size_t)blk * HW;
    float s = 0.f;
    for (int i = threadIdx.x; i < HW; i += 256) s += p[i];
    #pragma unroll
    for (int o = 16; o; o >>= 1) s += __shfl_xor_sync(0xFFFFFFFFu, s, o);
    __shared__ float wsum[8];
    if ((threadIdx.x & 31) == 0) wsum[threadIdx.x >> 5] = s;
    __syncthreads();
    if (threadIdx.x == 0) {
        float t = 0.f;
        #pragma unroll
        for (int w = 0; w < 8; w++) t += wsum[w];
        g_pooled[blk] = t * (1.0f / HW);
    }
}

// ---------------------------------------------------------------------------
// Kernel 2: routing (sigmoid) + aggregated bias.  One block.
// ---------------------------------------------------------------------------
__global__ void routing_kernel(const float* __restrict__ rw,
                               const float* __restrict__ rb,
                               const float* __restrict__ bias) {
    __shared__ float rt[B * E];
    int t = threadIdx.x;
    if (t < B * E) {
        int b = t / E, e = t % E;
        float acc = rb[e];
        const float* pp = g_pooled + b * C;
        const float* ww = rw + e * C;
        for (int c = 0; c < C; c++) acc += pp[c] * ww[c];
        float r = 1.0f / (1.0f + expf(-acc));
        rt[t] = r;
        g_routing[t] = r;
    }
    __syncthreads();
    int co = t;
    float be[E];
    #pragma unroll
    for (int e = 0; e < E; e++) be[e] = bias[e * C + co];
    #pragma unroll
    for (int b = 0; b < B; b++) {
        float a = 0.f;
        #pragma unroll
        for (int e = 0; e < E; e++) a += rt[b * E + e] * be[e];
        g_aggb[b * C + co] = a;
    }
}

// ---------------------------------------------------------------------------
// Kernel 3: weight aggregation -> g_aggw (tf32-rounded, f32 aggregation math).
// ---------------------------------------------------------------------------
__global__ void aggw_kernel(const float* __restrict__ weight) {
    __shared__ float rt[B * E];
    if (threadIdx.x < B * E) rt[threadIdx.x] = g_routing[threadIdx.x];
    __syncthreads();
    int i = blockIdx.x * blockDim.x + threadIdx.x;
    if (i >= WN) return;
    float w[E];
    #pragma unroll
    for (int e = 0; e < E; e++) w[e] = weight[(size_t)e * WN + i];
    #pragma unroll
    for (int b = 0; b < B; b++) {
        float a = 0.f;
        #pragma unroll
        for (int e = 0; e < E; e++) a += rt[b * E + e] * w[e];
        g_aggw[(size_t)b * WN + i] = __uint_as_float(tf32r(a));
    }
}

// ---------------------------------------------------------------------------
// Kernel 4: tf32 tensor-core implicit-GEMM conv (3x3, pad 1).
//
// Block tile: M = 64 couts, N = 128 pixels (2 output rows x 64 cols).
// K = Cin*9 = 2304, staged in chunks of 72 (8 ch x 9 taps), 9 k-steps/chunk.
// 128 threads = 4 warps.  Warp w: output row (w>>1), cols (w&1)*32..+32,
// all 64 couts: 4 m-tiles x 4 n-tiles = 16 MMAs (m16n8k8) per k-step.
//
// A staged FRAGMENT-MAJOR: ws_frag[(step*4+i)*32 + lane] is a float4 holding
// that lane's (a0,a1,a2,a3) -> one LDS.128 per (step, m-tile).
// B read from shifted window xs[8ch][4 rows][68] via precomputed offsets.
// ---------------------------------------------------------------------------
#define XPAD   68
#define KCH    8

__global__ __launch_bounds__(128, 3)
void conv_mma_kernel(const float* __restrict__ x, float* __restrict__ out) {
    __shared__ float xs[KCH * 4 * XPAD];          // [cl][r][col], col = gx+1
    __shared__ __align__(16) float ws_frag[9 * 4 * 32 * 4];  // fragment-major A

    const int b    = blockIdx.z;
    const int co0  = blockIdx.y * 64;
    const int y0   = blockIdx.x * 2;       // two output rows y0, y0+1
    const int tid  = threadIdx.x;
    const int wrp  = tid >> 5;
    const int lane = tid & 31;
    const int g    = lane >> 2;            // 0..7
    const int tg   = lane & 3;             // 0..3
    const int ry   = wrp >> 1;             // warp's output row (0/1)
    const int cb   = (wrp & 1) * 32;       // warp's col base

    float acc[4][4][4];
    #pragma unroll
    for (int i = 0; i < 4; i++)
        #pragma unroll
        for (int j = 0; j < 4; j++)
            #pragma unroll
            for (int c = 0; c < 4; c++) acc[i][j][c] = 0.f;

    // B smem offsets for 9 k-steps x 2 halves (n-tile 0; add j*8 at use).
    // kk = step*8 + tg + 4*h ; cl = kk/9 ; r = (kk%9)/3 ; s = kk%3
    int boff[9][2];
    #pragma unroll
    for (int step = 0; step < 9; step++) {
        #pragma unroll
        for (int h = 0; h < 2; h++) {
            int kk = step * 8 + tg + 4 * h;
            int cl = kk / 9;
            int j9 = kk - cl * 9;
            int r  = j9 / 3;
            int s  = j9 - r * 3;
            boff[step][h] = cl * (4 * XPAD) + (r + ry) * XPAD + (cb + g + s);
        }
    }

    const uint32_t* xsu = reinterpret_cast<const uint32_t*>(xs);

    for (int ci0 = 0; ci0 < C; ci0 += KCH) {
        // ---- stage x tile: 8 ch x 4 rows x 66 cols, tf32-rounded ----
        for (int idx = tid; idx < KCH * 4 * 66; idx += 128) {
            int cl  = idx / 264;
            int rem = idx - cl * 264;
            int r   = rem / 66;
            int col = rem - r * 66;
            int gy  = y0 + r - 1;
            int gx  = col - 1;
            float v = 0.f;
            if (gy >= 0 && gy < Hh && gx >= 0 && gx < Ww)
                v = x[(((size_t)b * C + ci0 + cl) * Hh + gy) * Ww + gx];
            xs[cl * (4 * XPAD) + r * XPAD + col] = __uint_as_float(tf32r(v));
        }
        // ---- stage weights fragment-major: 1152 float4 reads, scatter STS ----
        // float4 q covers (co = t/18, kk0 = (t%18)*4); all 4 elems share
        // (step, h); tg varies 0..3 -> 4 lanes, stride 16B.
        for (int t = tid; t < 1152; t += 128) {
            int co  = t / 18;
            int kk0 = (t - co * 18) * 4;
            const float4 w4 = *reinterpret_cast<const float4*>(
                g_aggw + ((size_t)(b * C + co0 + co) * C + ci0) * 9 + kk0);
            int step = kk0 >> 3;
            int h    = (kk0 >> 2) & 1;
            int i    = co >> 4;
            int gg   = co & 7;
            int hi   = (co >> 3) & 1;
            int v    = hi + 2 * h;
            float* base = ws_frag + (((step * 4 + i) * 32 + gg * 4) << 2) + v;
            base[0]  = w4.x;
            base[4]  = w4.y;
            base[8]  = w4.z;
            base[12] = w4.w;
        }
        __syncthreads();

        // ---- 9 MMA k-steps ----
        #pragma unroll
        for (int step = 0; step < 9; step++) {
            float4 a[4];
            #pragma unroll
            for (int i = 0; i < 4; i++)
                a[i] = *reinterpret_cast<const float4*>(
                    ws_frag + (((step * 4 + i) * 32 + lane) << 2));
            #pragma unroll
            for (int j = 0; j < 4; j++) {
                uint32_t b0 = xsu[boff[step][0] + j * 8];
                uint32_t b1 = xsu[boff[step][1] + j * 8];
                #pragma unroll
                for (int i = 0; i < 4; i++) {
                    asm volatile(
                        "mma.sync.aligned.m16n8k8.row.col.f32.tf32.tf32.f32 "
                        "{%0,%1,%2,%3}, {%4,%5,%6,%7}, {%8,%9}, {%0,%1,%2,%3};"
                        : "+f"(acc[i][j][0]), "+f"(acc[i][j][1]),
                          "+f"(acc[i][j][2]), "+f"(acc[i][j][3])
                        : "r"(__float_as_uint(a[i].x)), "r"(__float_as_uint(a[i].y)),
                          "r"(__float_as_uint(a[i].z)), "r"(__float_as_uint(a[i].w)),
                          "r"(b0), "r"(b1));
                }
            }
        }
        __syncthreads();
    }

    // ---- epilogue: bias + float2 stores ----
    const int y = y0 + ry;
    #pragma unroll
    for (int i = 0; i < 4; i++) {
        int co_a = co0 + i * 16 + g;
        int co_b = co_a + 8;
        float bba = g_aggb[b * C + co_a];
        float bbb = g_aggb[b * C + co_b];
        #pragma unroll
        for (int j = 0; j < 4; j++) {
            int col = cb + j * 8 + 2 * tg;
            float* pa = out + (((size_t)b * C + co_a) * Hh + y) * Ww + col;
            float* pb = out + (((size_t)b * C + co_b) * Hh + y) * Ww + col;
            *reinterpret_cast<float2*>(pa) =
                make_float2(acc[i][j][0] + bba, acc[i][j][1] + bba);
            *reinterpret_cast<float2*>(pb) =
                make_float2(acc[i][j][2] + bbb, acc[i][j][3] + bbb);
        }
    }
}

// ---------------------------------------------------------------------------
extern "C" void kernel_launch(void* const* d_in, const int* in_sizes, int n_in,
                              void* d_out, int out_size) {
    (void)in_sizes; (void)n_in; (void)out_size;
    const float* x      = (const float*)d_in[0];
    const float* weight = (const float*)d_in[1];
    const float* bias   = (const float*)d_in[2];
    const float* rw     = (const float*)d_in[3];
    const float* rb     = (const float*)d_in[4];
    float* out          = (float*)d_out;

    pool_kernel<<<B * C, 256>>>(x);
    routing_kernel<<<1, 256>>>(rw, rb, bias);
    aggw_kernel<<<(WN + 255) / 256, 256>>>(weight);
    conv_mma_kernel<<<dim3(Hh / 2, C / 64, B), 128>>>(x, out);
}

// round 7
// speedup vs baseline: 4.9633x; 2.2296x over previous
#include <cuda_runtime.h>
#include <math.h>
#include <stdint.h>

// Problem constants
#define B   16
#define C   256     // Cin == Cout
#define Hh  64
#define Ww  64
#define E   8
#define HW  (Hh * Ww)          // 4096
#define WN  (C * C * 9)        // per-expert weight elements = 589824

// Scratch (allocation-free rule: __device__ globals)
__device__ float g_pooled[B * C];
__device__ float g_routing[B * E];
__device__ float g_aggb[B * C];
__device__ float g_aggw[B * WN];          // fragment-major tf32 weights
__device__ float g_xcvt[B * C * HW];      // tf32-rounded x (64 MB)

// ---- helpers --------------------------------------------------------------
__device__ __forceinline__ uint32_t tf32r(float f) {
    uint32_t u;
    asm("cvt.rna.tf32.f32 %0, %1;" : "=r"(u) : "f"(f));
    return u;
}
__device__ __forceinline__ uint32_t smem_u32(const void* p) {
    return (uint32_t)__cvta_generic_to_shared(p);
}
#define CPA16(dst_u32, src_ptr) \
    asm volatile("cp.async.cg.shared.global [%0], [%1], 16;" \
                 :: "r"(dst_u32), "l"(src_ptr) : "memory")

// ---------------------------------------------------------------------------
// Kernel 1: global average pool.  One block per (b, ci).
// ---------------------------------------------------------------------------
__global__ void pool_kernel(const float* __restrict__ x) {
    int blk = blockIdx.x;
    const float* p = x + (size_t)blk * HW;
    float s = 0.f;
    for (int i = threadIdx.x; i < HW; i += 256) s += p[i];
    #pragma unroll
    for (int o = 16; o; o >>= 1) s += __shfl_xor_sync(0xFFFFFFFFu, s, o);
    __shared__ float wsum[8];
    if ((threadIdx.x & 31) == 0) wsum[threadIdx.x >> 5] = s;
    __syncthreads();
    if (threadIdx.x == 0) {
        float t = 0.f;
        #pragma unroll
        for (int w = 0; w < 8; w++) t += wsum[w];
        g_pooled[blk] = t * (1.0f / HW);
    }
}

// ---------------------------------------------------------------------------
// Kernel 2: routing (sigmoid) + aggregated bias.  One block.
// ---------------------------------------------------------------------------
__global__ void routing_kernel(const float* __restrict__ rw,
                               const float* __restrict__ rb,
                               const float* __restrict__ bias) {
    __shared__ float rt[B * E];
    int t = threadIdx.x;
    if (t < B * E) {
        int b = t / E, e = t % E;
        float acc = rb[e];
        const float* pp = g_pooled + b * C;
        const float* ww = rw + e * C;
        for (int c = 0; c < C; c++) acc += pp[c] * ww[c];
        float r = 1.0f / (1.0f + expf(-acc));
        rt[t] = r;
        g_routing[t] = r;
    }
    __syncthreads();
    int co = t;
    float be[E];
    #pragma unroll
    for (int e = 0; e < E; e++) be[e] = bias[e * C + co];
    #pragma unroll
    for (int b = 0; b < B; b++) {
        float a = 0.f;
        #pragma unroll
        for (int e = 0; e < E; e++) a += rt[b * E + e] * be[e];
        g_aggb[b * C + co] = a;
    }
}

// ---------------------------------------------------------------------------
// Kernel 3: weight aggregation directly into FRAGMENT-MAJOR layout.
// Dest (per b): [co_blk(4)][chunk(32)][p(4608)],
//   p = ((step*4 + i)*32 + g*4 + tg)*4 + v,  v = hi + 2*h
//   co_local = i*16 + hi*8 + g ; kk = step*8 + h*4 + tg ;
//   ci = chunk*8 + kk/9 ; tap = kk%9.
// Writes are coalesced per b; reads are gathered (L2-served).
// ---------------------------------------------------------------------------
__global__ void aggw_kernel(const float* __restrict__ weight) {
    __shared__ float rt[B * E];
    if (threadIdx.x < B * E) rt[threadIdx.x] = g_routing[threadIdx.x];
    __syncthreads();
    int idx = blockIdx.x * blockDim.x + threadIdx.x;
    if (idx >= WN) return;

    int co_blk = idx / 147456;          // 32*4608
    int rem    = idx - co_blk * 147456;
    int chunk  = rem / 4608;
    int p      = rem - chunk * 4608;
    int v    = p & 3;
    int q    = p >> 2;
    int tg   = q & 3;
    int g    = (q >> 2) & 7;
    int i    = (q >> 5) & 3;
    int step = q >> 7;
    int hi = v & 1;
    int h  = v >> 1;
    int co_local = i * 16 + hi * 8 + g;
    int kk = step * 8 + h * 4 + tg;
    int ci = chunk * 8 + kk / 9;
    int tap = kk % 9;
    size_t src = ((size_t)(co_blk * 64 + co_local) * C + ci) * 9 + tap;

    float w[E];
    #pragma unroll
    for (int e = 0; e < E; e++) w[e] = weight[(size_t)e * WN + src];
    #pragma unroll
    for (int b = 0; b < B; b++) {
        float a = 0.f;
        #pragma unroll
        for (int e = 0; e < E; e++) a += rt[b * E + e] * w[e];
        g_aggw[(size_t)b * WN + idx] = __uint_as_float(tf32r(a));
    }
}

// ---------------------------------------------------------------------------
// Kernel 3b: x -> tf32(rna) pre-pass (vectorized).
// ---------------------------------------------------------------------------
__global__ void xcvt_kernel(const float* __restrict__ x) {
    int i = blockIdx.x * blockDim.x + threadIdx.x;   // float4 index
    float4 v = reinterpret_cast<const float4*>(x)[i];
    float4 o;
    o.x = __uint_as_float(tf32r(v.x));
    o.y = __uint_as_float(tf32r(v.y));
    o.z = __uint_as_float(tf32r(v.z));
    o.w = __uint_as_float(tf32r(v.w));
    reinterpret_cast<float4*>(g_xcvt)[i] = o;
}

// ---------------------------------------------------------------------------
// Kernel 4: tf32 tensor-core implicit-GEMM conv (3x3, pad 1).
// Block tile M=64 couts, N=128 px (2 rows x 64 cols); K chunked by 72.
// All staging is cp.async 16B from pre-permuted / pre-converted buffers.
// xs rows: col = gx + 4 (interior 16B-aligned); halo cols 3/68 are constant 0.
// ---------------------------------------------------------------------------
#define XROW 72
#define KCH  8

__global__ __launch_bounds__(128, 3)
void conv_mma_kernel(const float* __restrict__ xcvt, float* __restrict__ out) {
    __shared__ __align__(16) float xs[KCH * 4 * XROW];       // 9216 B
    __shared__ __align__(16) float ws_frag[4608];            // 18432 B

    const int b    = blockIdx.z;
    const int cob  = blockIdx.y;           // co block 0..3
    const int y0   = blockIdx.x * 2;
    const int tid  = threadIdx.x;
    const int wrp  = tid >> 5;
    const int lane = tid & 31;
    const int g    = lane >> 2;
    const int tg   = lane & 3;
    const int ry   = wrp >> 1;
    const int cb   = (wrp & 1) * 32;

    float acc[4][4][4];
    #pragma unroll
    for (int i = 0; i < 4; i++)
        #pragma unroll
        for (int j = 0; j < 4; j++)
            #pragma unroll
            for (int c = 0; c < 4; c++) acc[i][j][c] = 0.f;

    // B smem offsets (floats): kk = step*8 + tg + 4*h
    int boff[9][2];
    #pragma unroll
    for (int step = 0; step < 9; step++) {
        #pragma unroll
        for (int h = 0; h < 2; h++) {
            int kk = step * 8 + tg + 4 * h;
            int cl = kk / 9;
            int j9 = kk - cl * 9;
            int r  = j9 / 3;
            int s  = j9 - r * 3;
            boff[step][h] = cl * (4 * XROW) + (r + ry) * XROW + (cb + g + s + 3);
        }
    }

    const uint32_t xs_u = smem_u32(xs);
    const uint32_t ws_u = smem_u32(ws_frag);
    const uint32_t* xsu = reinterpret_cast<const uint32_t*>(xs);

    // halo columns (gx=-1 -> col 3, gx=64 -> col 68) are always zero
    for (int t = tid; t < 64; t += 128) {
        int row = t >> 1;
        xs[row * XROW + ((t & 1) ? 68 : 3)] = 0.f;
    }

    const float* wsrc_base = g_aggw + (size_t)b * WN + (size_t)cob * 147456;

    for (int chunk = 0; chunk < 32; chunk++) {
        __syncthreads();    // previous compute done; smem reusable
        // ---- weights: contiguous 18KB copy, 9 x cp.async/thread ----
        const float* wsrc = wsrc_base + chunk * 4608;
        #pragma unroll
        for (int t = tid; t < 1152; t += 128)
            CPA16(ws_u + t * 16, wsrc + t * 4);
        // ---- x tile: 8ch x 4 rows x 64 interior cols, 4 x cp.async/thread ----
        const int ci0 = chunk * 8;
        #pragma unroll
        for (int t = tid; t < 512; t += 128) {
            int row_id = t >> 4;            // 0..31 = cl*4 + r
            int vec    = t & 15;
            int cl = row_id >> 2;
            int r  = row_id & 3;
            int gy = y0 + r - 1;
            int doff = cl * (4 * XROW) + r * XROW + 4 + vec * 4;
            if ((unsigned)gy < (unsigned)Hh) {
                CPA16(xs_u + doff * 4,
                      xcvt + (((size_t)b * C + ci0 + cl) * Hh + gy) * Ww + vec * 4);
            } else {
                *reinterpret_cast<float4*>(xs + doff) = make_float4(0.f, 0.f, 0.f, 0.f);
            }
        }
        asm volatile("cp.async.commit_group;" ::: "memory");
        asm volatile("cp.async.wait_group 0;" ::: "memory");
        __syncthreads();

        // ---- 9 MMA k-steps ----
        #pragma unroll
        for (int step = 0; step < 9; step++) {
            float4 a[4];
            #pragma unroll
            for (int i = 0; i < 4; i++)
                a[i] = *reinterpret_cast<const float4*>(
                    ws_frag + (((step * 4 + i) * 32 + lane) << 2));
            #pragma unroll
            for (int j = 0; j < 4; j++) {
                uint32_t b0 = xsu[boff[step][0] + j * 8];
                uint32_t b1 = xsu[boff[step][1] + j * 8];
                #pragma unroll
                for (int i = 0; i < 4; i++) {
                    asm volatile(
                        "mma.sync.aligned.m16n8k8.row.col.f32.tf32.tf32.f32 "
                        "{%0,%1,%2,%3}, {%4,%5,%6,%7}, {%8,%9}, {%0,%1,%2,%3};"
                        : "+f"(acc[i][j][0]), "+f"(acc[i][j][1]),
                          "+f"(acc[i][j][2]), "+f"(acc[i][j][3])
                        : "r"(__float_as_uint(a[i].x)), "r"(__float_as_uint(a[i].y)),
                          "r"(__float_as_uint(a[i].z)), "r"(__float_as_uint(a[i].w)),
                          "r"(b0), "r"(b1));
                }
            }
        }
    }

    // ---- epilogue: bias + float2 stores ----
    const int y   = y0 + ry;
    const int co0 = cob * 64;
    #pragma unroll
    for (int i = 0; i < 4; i++) {
        int co_a = co0 + i * 16 + g;
        int co_b = co_a + 8;
        float bba = g_aggb[b * C + co_a];
        float bbb = g_aggb[b * C + co_b];
        #pragma unroll
        for (int j = 0; j < 4; j++) {
            int col = cb + j * 8 + 2 * tg;
            float* pa = out + (((size_t)b * C + co_a) * Hh + y) * Ww + col;
            float* pb = out + (((size_t)b * C + co_b) * Hh + y) * Ww + col;
            *reinterpret_cast<float2*>(pa) =
                make_float2(acc[i][j][0] + bba, acc[i][j][1] + bba);
            *reinterpret_cast<float2*>(pb) =
                make_float2(acc[i][j][2] + bbb, acc[i][j][3] + bbb);
        }
    }
}

// ---------------------------------------------------------------------------
extern "C" void kernel_launch(void* const* d_in, const int* in_sizes, int n_in,
                              void* d_out, int out_size) {
    (void)in_sizes; (void)n_in; (void)out_size;
    const float* x      = (const float*)d_in[0];
    const float* weight = (const float*)d_in[1];
    const float* bias   = (const float*)d_in[2];
    const float* rw     = (const float*)d_in[3];
    const float* rb     = (const float*)d_in[4];
    float* out          = (float*)d_out;

    pool_kernel<<<B * C, 256>>>(x);
    routing_kernel<<<1, 256>>>(rw, rb, bias);
    aggw_kernel<<<(WN + 255) / 256, 256>>>(weight);
    xcvt_kernel<<<(B * C * HW / 4) / 256, 256>>>(x);

    float* xcvt_dev = nullptr;
    cudaGetSymbolAddress((void**)&xcvt_dev, g_xcvt);
    conv_mma_kernel<<<dim3(Hh / 2, C / 64, B), 128>>>(xcvt_dev, out);
}

// round 9
// speedup vs baseline: 5.1142x; 1.0304x over previous
#include <cuda_runtime.h>
#include <math.h>
#include <stdint.h>

// Problem constants
#define B   16
#define C   256     // Cin == Cout
#define Hh  64
#define Ww  64
#define E   8
#define HW  (Hh * Ww)          // 4096
#define WN  (C * C * 9)        // per-expert weight elements = 589824

// Scratch (allocation-free rule: __device__ globals)
__device__ float g_pooled[B * C];
__device__ float g_routing[B * E];
__device__ float g_aggb[B * C];
__device__ float g_aggw[B * WN];          // fragment-major tf32 weights
__device__ float g_xcvt[B * C * HW];      // tf32-rounded x (64 MB)

// ---- helpers --------------------------------------------------------------
__device__ __forceinline__ uint32_t tf32r(float f) {
    uint32_t u;
    asm("cvt.rna.tf32.f32 %0, %1;" : "=r"(u) : "f"(f));
    return u;
}
__device__ __forceinline__ uint32_t smem_u32(const void* p) {
    return (uint32_t)__cvta_generic_to_shared(p);
}
#define CPA16(dst_u32, src_ptr) \
    asm volatile("cp.async.cg.shared.global [%0], [%1], 16;" \
                 :: "r"(dst_u32), "l"(src_ptr) : "memory")

// ---------------------------------------------------------------------------
// Kernel 1: global average pool.  One block per (b, ci).
// ---------------------------------------------------------------------------
__global__ void pool_kernel(const float* __restrict__ x) {
    int blk = blockIdx.x;
    const float* p = x + (size_t)blk * HW;
    float s = 0.f;
    for (int i = threadIdx.x; i < HW; i += 256) s += p[i];
    #pragma unroll
    for (int o = 16; o; o >>= 1) s += __shfl_xor_sync(0xFFFFFFFFu, s, o);
    __shared__ float wsum[8];
    if ((threadIdx.x & 31) == 0) wsum[threadIdx.x >> 5] = s;
    __syncthreads();
    if (threadIdx.x == 0) {
        float t = 0.f;
        #pragma unroll
        for (int w = 0; w < 8; w++) t += wsum[w];
        g_pooled[blk] = t * (1.0f / HW);
    }
}

// ---------------------------------------------------------------------------
// Kernel 2: routing (sigmoid) + aggregated bias.  One block.
// ---------------------------------------------------------------------------
__global__ void routing_kernel(const float* __restrict__ rw,
                               const float* __restrict__ rb,
                               const float* __restrict__ bias) {
    __shared__ float rt[B * E];
    int t = threadIdx.x;
    if (t < B * E) {
        int b = t / E, e = t % E;
        float acc = rb[e];
        const float* pp = g_pooled + b * C;
        const float* ww = rw + e * C;
        for (int c = 0; c < C; c++) acc += pp[c] * ww[c];
        float r = 1.0f / (1.0f + expf(-acc));
        rt[t] = r;
        g_routing[t] = r;
    }
    __syncthreads();
    int co = t;
    float be[E];
    #pragma unroll
    for (int e = 0; e < E; e++) be[e] = bias[e * C + co];
    #pragma unroll
    for (int b = 0; b < B; b++) {
        float a = 0.f;
        #pragma unroll
        for (int e = 0; e < E; e++) a += rt[b * E + e] * be[e];
        g_aggb[b * C + co] = a;
    }
}

// ---------------------------------------------------------------------------
// Kernel 3: weight aggregation directly into FRAGMENT-MAJOR layout.
// Dest (per b): [co_blk(4)][chunk(32)][p(4608)],
//   p = ((step*4 + i)*32 + g*4 + tg)*4 + v,  v = hi + 2*h
//   co_local = i*16 + hi*8 + g ; kk = step*8 + h*4 + tg ;
//   ci = chunk*8 + kk/9 ; tap = kk%9.
// ---------------------------------------------------------------------------
__global__ void aggw_kernel(const float* __restrict__ weight) {
    __shared__ float rt[B * E];
    if (threadIdx.x < B * E) rt[threadIdx.x] = g_routing[threadIdx.x];
    __syncthreads();
    int idx = blockIdx.x * blockDim.x + threadIdx.x;
    if (idx >= WN) return;

    int co_blk = idx / 147456;          // 32*4608
    int rem    = idx - co_blk * 147456;
    int chunk  = rem / 4608;
    int p      = rem - chunk * 4608;
    int v    = p & 3;
    int q    = p >> 2;
    int tg   = q & 3;
    int g    = (q >> 2) & 7;
    int i    = (q >> 5) & 3;
    int step = q >> 7;
    int hi = v & 1;
    int h  = v >> 1;
    int co_local = i * 16 + hi * 8 + g;
    int kk = step * 8 + h * 4 + tg;
    int ci = chunk * 8 + kk / 9;
    int tap = kk % 9;
    size_t src = ((size_t)(co_blk * 64 + co_local) * C + ci) * 9 + tap;

    float w[E];
    #pragma unroll
    for (int e = 0; e < E; e++) w[e] = weight[(size_t)e * WN + src];
    #pragma unroll
    for (int b = 0; b < B; b++) {
        float a = 0.f;
        #pragma unroll
        for (int e = 0; e < E; e++) a += rt[b * E + e] * w[e];
        g_aggw[(size_t)b * WN + idx] = __uint_as_float(tf32r(a));
    }
}

// ---------------------------------------------------------------------------
// Kernel 3b: x -> tf32(rna) pre-pass (vectorized).
// ---------------------------------------------------------------------------
__global__ void xcvt_kernel(const float* __restrict__ x) {
    int i = blockIdx.x * blockDim.x + threadIdx.x;   // float4 index
    float4 v = reinterpret_cast<const float4*>(x)[i];
    float4 o;
    o.x = __uint_as_float(tf32r(v.x));
    o.y = __uint_as_float(tf32r(v.y));
    o.z = __uint_as_float(tf32r(v.z));
    o.w = __uint_as_float(tf32r(v.w));
    reinterpret_cast<float4*>(g_xcvt)[i] = o;
}

// ---------------------------------------------------------------------------
// Kernel 4: tf32 tensor-core implicit-GEMM conv (3x3, pad 1).
// Block tile M=64 couts, N=128 px (2 rows x 64 cols); K chunked by 72.
// 2-stage cp.async double buffer in DYNAMIC shared memory (55296 B):
//   layout: [ xs buf0 | xs buf1 | ws buf0 | ws buf1 ]
// ---------------------------------------------------------------------------
#define XROW  72
#define KCH   8
#define XS_N  (KCH * 4 * XROW)   // 2304 floats per x buffer
#define WS_N  4608               // floats per weight buffer
#define SMEM_BYTES ((2 * XS_N + 2 * WS_N) * 4)   // 55296

__global__ __launch_bounds__(128, 3)
void conv_mma_kernel(const float* __restrict__ xcvt, float* __restrict__ out) {
    extern __shared__ __align__(16) float smem[];
    float* xs      = smem;                 // 2 * XS_N
    float* ws_frag = smem + 2 * XS_N;      // 2 * WS_N

    const int b    = blockIdx.z;
    const int cob  = blockIdx.y;           // co block 0..3
    const int y0   = blockIdx.x * 2;
    const int tid  = threadIdx.x;
    const int wrp  = tid >> 5;
    const int lane = tid & 31;
    const int g    = lane >> 2;
    const int tg   = lane & 3;
    const int ry   = wrp >> 1;
    const int cb   = (wrp & 1) * 32;

    float acc[4][4][4];
    #pragma unroll
    for (int i = 0; i < 4; i++)
        #pragma unroll
        for (int j = 0; j < 4; j++)
            #pragma unroll
            for (int c = 0; c < 4; c++) acc[i][j][c] = 0.f;

    // B smem offsets (floats, within one buffer): kk = step*8 + tg + 4*h
    int boff[9][2];
    #pragma unroll
    for (int step = 0; step < 9; step++) {
        #pragma unroll
        for (int h = 0; h < 2; h++) {
            int kk = step * 8 + tg + 4 * h;
            int cl = kk / 9;
            int j9 = kk - cl * 9;
            int r  = j9 / 3;
            int s  = j9 - r * 3;
            boff[step][h] = cl * (4 * XROW) + (r + ry) * XROW + (cb + g + s + 3);
        }
    }

    const uint32_t xs_u = smem_u32(xs);
    const uint32_t ws_u = smem_u32(ws_frag);
    const uint32_t* xsu = reinterpret_cast<const uint32_t*>(xs);

    // halo columns (gx=-1 -> col 3, gx=64 -> col 68) are always zero, both bufs
    for (int t = tid; t < 128; t += 128) {
        int bf  = t >> 6;
        int row = (t & 63) >> 1;
        xs[bf * XS_N + row * XROW + ((t & 1) ? 68 : 3)] = 0.f;
    }

    const float* wsrc_base = g_aggw + (size_t)b * WN + (size_t)cob * 147456;

    // ---- staging lambda (cp.async into buffer bf for k-chunk 'chunk') ----
    auto stage = [&](int chunk, int bf) {
        const float* wsrc = wsrc_base + chunk * WS_N;
        const uint32_t wdst = ws_u + bf * (WS_N * 4);
        #pragma unroll
        for (int t = tid; t < 1152; t += 128)
            CPA16(wdst + t * 16, wsrc + t * 4);
        const int ci0 = chunk * 8;
        const uint32_t xdst = xs_u + bf * (XS_N * 4);
        #pragma unroll
        for (int t = tid; t < 512; t += 128) {
            int row_id = t >> 4;            // cl*4 + r
            int vec    = t & 15;
            int cl = row_id >> 2;
            int r  = row_id & 3;
            int gy = y0 + r - 1;
            int doff = cl * (4 * XROW) + r * XROW + 4 + vec * 4;
            if ((unsigned)gy < (unsigned)Hh) {
                CPA16(xdst + doff * 4,
                      xcvt + (((size_t)b * C + ci0 + cl) * Hh + gy) * Ww + vec * 4);
            } else {
                *reinterpret_cast<float4*>(&xs[bf * XS_N + doff]) =
                    make_float4(0.f, 0.f, 0.f, 0.f);
            }
        }
        asm volatile("cp.async.commit_group;" ::: "memory");
    };

    // ---- prologue: stage chunk 0 ----
    stage(0, 0);

    for (int chunk = 0; chunk < 32; chunk++) {
        const int cur = chunk & 1;
        if (chunk + 1 < 32) {
            stage(chunk + 1, cur ^ 1);
            asm volatile("cp.async.wait_group 1;" ::: "memory");
        } else {
            asm volatile("cp.async.wait_group 0;" ::: "memory");
        }
        __syncthreads();

        const float* wbuf = ws_frag + cur * WS_N;
        const int xbase = cur * XS_N;

        #pragma unroll
        for (int step = 0; step < 9; step++) {
            float4 a[4];
            #pragma unroll
            for (int i = 0; i < 4; i++)
                a[i] = *reinterpret_cast<const float4*>(
                    wbuf + (((step * 4 + i) * 32 + lane) << 2));
            #pragma unroll
            for (int j = 0; j < 4; j++) {
                uint32_t b0 = xsu[xbase + boff[step][0] + j * 8];
                uint32_t b1 = xsu[xbase + boff[step][1] + j * 8];
                #pragma unroll
                for (int i = 0; i < 4; i++) {
                    asm volatile(
                        "mma.sync.aligned.m16n8k8.row.col.f32.tf32.tf32.f32 "
                        "{%0,%1,%2,%3}, {%4,%5,%6,%7}, {%8,%9}, {%0,%1,%2,%3};"
                        : "+f"(acc[i][j][0]), "+f"(acc[i][j][1]),
                          "+f"(acc[i][j][2]), "+f"(acc[i][j][3])
                        : "r"(__float_as_uint(a[i].x)), "r"(__float_as_uint(a[i].y)),
                          "r"(__float_as_uint(a[i].z)), "r"(__float_as_uint(a[i].w)),
                          "r"(b0), "r"(b1));
                }
            }
        }
        __syncthreads();   // protect buffer re-staged next iteration
    }

    // ---- epilogue: bias + float2 stores ----
    const int y   = y0 + ry;
    const int co0 = cob * 64;
    #pragma unroll
    for (int i = 0; i < 4; i++) {
        int co_a = co0 + i * 16 + g;
        int co_b = co_a + 8;
        float bba = g_aggb[b * C + co_a];
        float bbb = g_aggb[b * C + co_b];
        #pragma unroll
        for (int j = 0; j < 4; j++) {
            int col = cb + j * 8 + 2 * tg;
            float* pa = out + (((size_t)b * C + co_a) * Hh + y) * Ww + col;
            float* pb = out + (((size_t)b * C + co_b) * Hh + y) * Ww + col;
            *reinterpret_cast<float2*>(pa) =
                make_float2(acc[i][j][0] + bba, acc[i][j][1] + bba);
            *reinterpret_cast<float2*>(pb) =
                make_float2(acc[i][j][2] + bbb, acc[i][j][3] + bbb);
        }
    }
}

// ---------------------------------------------------------------------------
extern "C" void kernel_launch(void* const* d_in, const int* in_sizes, int n_in,
                              void* d_out, int out_size) {
    (void)in_sizes; (void)n_in; (void)out_size;
    const float* x      = (const float*)d_in[0];
    const float* weight = (const float*)d_in[1];
    const float* bias   = (const float*)d_in[2];
    const float* rw     = (const float*)d_in[3];
    const float* rb     = (const float*)d_in[4];
    float* out          = (float*)d_out;

    // Opt-in to >48KB dynamic shared memory (attribute set, not an allocation;
    // idempotent and deterministic on every call).
    cudaFuncSetAttribute(conv_mma_kernel,
                         cudaFuncAttributeMaxDynamicSharedMemorySize, SMEM_BYTES);

    pool_kernel<<<B * C, 256>>>(x);
    routing_kernel<<<1, 256>>>(rw, rb, bias);
    aggw_kernel<<<(WN + 255) / 256, 256>>>(weight);
    xcvt_kernel<<<(B * C * HW / 4) / 256, 256>>>(x);

    float* xcvt_dev = nullptr;
    cudaGetSymbolAddress((void**)&xcvt_dev, g_xcvt);
    conv_mma_kernel<<<dim3(Hh / 2, C / 64, B), 128, SMEM_BYTES>>>(xcvt_dev, out);
}

// round 15
// speedup vs baseline: 5.2506x; 1.0267x over previous
#include <cuda_runtime.h>
#include <math.h>
#include <stdint.h>

// Problem constants
#define B   16
#define C   256     // Cin == Cout
#define Hh  64
#define Ww  64
#define E   8
#define HW  (Hh * Ww)          // 4096
#define WN  (C * C * 9)        // per-expert weight elements = 589824

// Scratch (allocation-free rule: __device__ globals)
__device__ float g_pooled[B * C];
__device__ float g_routing[B * E];
__device__ float g_aggb[B * C];
__device__ float g_aggw[B * WN];          // fragment-major tf32 weights
__device__ float g_xcvt[B * C * HW];      // tf32-rounded x (64 MB)

// ---- helpers --------------------------------------------------------------
__device__ __forceinline__ uint32_t tf32r(float f) {
    uint32_t u;
    asm("cvt.rna.tf32.f32 %0, %1;" : "=r"(u) : "f"(f));
    return u;
}
__device__ __forceinline__ uint32_t smem_u32(const void* p) {
    return (uint32_t)__cvta_generic_to_shared(p);
}
#define CPA16(dst_u32, src_ptr) \
    asm volatile("cp.async.cg.shared.global [%0], [%1], 16;" \
                 :: "r"(dst_u32), "l"(src_ptr) : "memory")

// ---------------------------------------------------------------------------
// Kernel 1: global average pool.  One block per (b, ci).
// ---------------------------------------------------------------------------
__global__ void pool_kernel(const float* __restrict__ x) {
    int blk = blockIdx.x;
    const float* p = x + (size_t)blk * HW;
    float s = 0.f;
    for (int i = threadIdx.x; i < HW; i += 256) s += p[i];
    #pragma unroll
    for (int o = 16; o; o >>= 1) s += __shfl_xor_sync(0xFFFFFFFFu, s, o);
    __shared__ float wsum[8];
    if ((threadIdx.x & 31) == 0) wsum[threadIdx.x >> 5] = s;
    __syncthreads();
    if (threadIdx.x == 0) {
        float t = 0.f;
        #pragma unroll
        for (int w = 0; w < 8; w++) t += wsum[w];
        g_pooled[blk] = t * (1.0f / HW);
    }
}

// ---------------------------------------------------------------------------
// Kernel 2: routing (sigmoid) + aggregated bias.  One block.
// ---------------------------------------------------------------------------
__global__ void routing_kernel(const float* __restrict__ rw,
                               const float* __restrict__ rb,
                               const float* __restrict__ bias) {
    __shared__ float rt[B * E];
    int t = threadIdx.x;
    if (t < B * E) {
        int b = t / E, e = t % E;
        float acc = rb[e];
        const float* pp = g_pooled + b * C;
        const float* ww = rw + e * C;
        for (int c = 0; c < C; c++) acc += pp[c] * ww[c];
        float r = 1.0f / (1.0f + expf(-acc));
        rt[t] = r;
        g_routing[t] = r;
    }
    __syncthreads();
    int co = t;
    float be[E];
    #pragma unroll
    for (int e = 0; e < E; e++) be[e] = bias[e * C + co];
    #pragma unroll
    for (int b = 0; b < B; b++) {
        float a = 0.f;
        #pragma unroll
        for (int e = 0; e < E; e++) a += rt[b * E + e] * be[e];
        g_aggb[b * C + co] = a;
    }
}

// ---------------------------------------------------------------------------
// Kernel 3: weight aggregation directly into FRAGMENT-MAJOR layout.
// Dest (per b): [co_blk(4)][chunk(32)][p(4608)],
//   p = ((step*4 + i)*32 + g*4 + tg)*4 + v,  v = hi + 2*h
//   co_local = i*16 + hi*8 + g ; kk = step*8 + h*4 + tg ;
//   ci = chunk*8 + kk/9 ; tap = kk%9.
// ---------------------------------------------------------------------------
__global__ void aggw_kernel(const float* __restrict__ weight) {
    __shared__ float rt[B * E];
    if (threadIdx.x < B * E) rt[threadIdx.x] = g_routing[threadIdx.x];
    __syncthreads();
    int idx = blockIdx.x * blockDim.x + threadIdx.x;
    if (idx >= WN) return;

    int co_blk = idx / 147456;          // 32*4608
    int rem    = idx - co_blk * 147456;
    int chunk  = rem / 4608;
    int p      = rem - chunk * 4608;
    int v    = p & 3;
    int q    = p >> 2;
    int tg   = q & 3;
    int g    = (q >> 2) & 7;
    int i    = (q >> 5) & 3;
    int step = q >> 7;
    int hi = v & 1;
    int h  = v >> 1;
    int co_local = i * 16 + hi * 8 + g;
    int kk = step * 8 + h * 4 + tg;
    int ci = chunk * 8 + kk / 9;
    int tap = kk % 9;
    size_t src = ((size_t)(co_blk * 64 + co_local) * C + ci) * 9 + tap;

    float w[E];
    #pragma unroll
    for (int e = 0; e < E; e++) w[e] = weight[(size_t)e * WN + src];
    #pragma unroll
    for (int b = 0; b < B; b++) {
        float a = 0.f;
        #pragma unroll
        for (int e = 0; e < E; e++) a += rt[b * E + e] * w[e];
        g_aggw[(size_t)b * WN + idx] = __uint_as_float(tf32r(a));
    }
}

// ---------------------------------------------------------------------------
// Kernel 3b: x -> tf32(rna) pre-pass (vectorized).
// ---------------------------------------------------------------------------
__global__ void xcvt_kernel(const float* __restrict__ x) {
    int i = blockIdx.x * blockDim.x + threadIdx.x;   // float4 index
    float4 v = reinterpret_cast<const float4*>(x)[i];
    float4 o;
    o.x = __uint_as_float(tf32r(v.x));
    o.y = __uint_as_float(tf32r(v.y));
    o.z = __uint_as_float(tf32r(v.z));
    o.w = __uint_as_float(tf32r(v.w));
    reinterpret_cast<float4*>(g_xcvt)[i] = o;
}

// ---------------------------------------------------------------------------
// Kernel 4: tf32 mma.sync implicit-GEMM conv (3x3, pad 1).
// Block tile M=64 couts, N=256 px (4 rows x 64 cols); K chunked by 72.
// 128 threads = 4 warps; warp w owns output row w: 8 n-tiles x 4 m-tiles
// = 32 MMAs per k-step (96 operand-bytes/MMA, half of the 2-row version).
// 2-stage cp.async double buffer in dynamic smem (64512 B).
//   layout: [ xs buf0 | xs buf1 | ws buf0 | ws buf1 ]
// xs: [8 ch][6 rows][72], rows = y0-1 .. y0+4; halo cols 3/68 constant zero.
// ---------------------------------------------------------------------------
#define XROW  72
#define KCH   8
#define XS_N  (KCH * 6 * XROW)   // 3456 floats per x buffer
#define WS_N  4608               // floats per weight buffer
#define SMEM_BYTES ((2 * XS_N + 2 * WS_N) * 4)   // 64512

__global__ __launch_bounds__(128)
void conv_mma_kernel(const float* __restrict__ xcvt, float* __restrict__ out) {
    extern __shared__ __align__(16) float smem[];
    float* xs      = smem;                 // 2 * XS_N
    float* ws_frag = smem + 2 * XS_N;      // 2 * WS_N

    const int b    = blockIdx.z;
    const int cob  = blockIdx.y;           // co block 0..3
    const int y0   = blockIdx.x * 4;
    const int tid  = threadIdx.x;
    const int wrp  = tid >> 5;             // warp = output row (0..3)
    const int lane = tid & 31;
    const int g    = lane >> 2;
    const int tg   = lane & 3;

    float acc[4][8][4];
    #pragma unroll
    for (int i = 0; i < 4; i++)
        #pragma unroll
        for (int j = 0; j < 8; j++)
            #pragma unroll
            for (int c = 0; c < 4; c++) acc[i][j][c] = 0.f;

    // B smem offsets (floats, within one buffer, j=0): kk = step*8 + tg + 4*h
    int boff[9][2];
    #pragma unroll
    for (int step = 0; step < 9; step++) {
        #pragma unroll
        for (int h = 0; h < 2; h++) {
            int kk = step * 8 + tg + 4 * h;
            int cl = kk / 9;
            int j9 = kk - cl * 9;
            int r  = j9 / 3;
            int s  = j9 - r * 3;
            boff[step][h] = cl * (6 * XROW) + (r + wrp) * XROW + (g + s + 3);
        }
    }

    const uint32_t xs_u = smem_u32(xs);
    const uint32_t ws_u = smem_u32(ws_frag);
    const uint32_t* xsu = reinterpret_cast<const uint32_t*>(xs);

    // halo columns (gx=-1 -> col 3, gx=64 -> col 68): zero in both buffers
    for (int t = tid; t < 192; t += 128) {
        int bf  = t / 96;
        int row = (t % 96) >> 1;          // 0..47 = cl*6 + r
        xs[bf * XS_N + row * XROW + ((t & 1) ? 68 : 3)] = 0.f;
    }

    const float* wsrc_base = g_aggw + (size_t)b * WN + (size_t)cob * 147456;

    // ---- staging (cp.async into buffer bf for k-chunk 'chunk') ----
    auto stage = [&](int chunk, int bf) {
        const float* wsrc = wsrc_base + chunk * WS_N;
        const uint32_t wdst = ws_u + bf * (WS_N * 4);
        #pragma unroll
        for (int t = tid; t < 1152; t += 128)
            CPA16(wdst + t * 16, wsrc + t * 4);
        const int ci0 = chunk * 8;
        const uint32_t xdst = xs_u + bf * (XS_N * 4);
        #pragma unroll
        for (int t = tid; t < 768; t += 128) {
            int row_id = t >> 4;            // 0..47 = cl*6 + r
            int vec    = t & 15;
            int cl = row_id / 6;
            int r  = row_id - cl * 6;
            int gy = y0 + r - 1;
            int doff = cl * (6 * XROW) + r * XROW + 4 + vec * 4;
            if ((unsigned)gy < (unsigned)Hh) {
                CPA16(xdst + doff * 4,
                      xcvt + (((size_t)b * C + ci0 + cl) * Hh + gy) * Ww + vec * 4);
            } else {
                *reinterpret_cast<float4*>(&xs[bf * XS_N + doff]) =
                    make_float4(0.f, 0.f, 0.f, 0.f);
            }
        }
        asm volatile("cp.async.commit_group;" ::: "memory");
    };

    // ---- prologue: stage chunk 0 ----
    stage(0, 0);

    for (int chunk = 0; chunk < 32; chunk++) {
        const int cur = chunk & 1;
        if (chunk + 1 < 32) {
            stage(chunk + 1, cur ^ 1);
            asm volatile("cp.async.wait_group 1;" ::: "memory");
        } else {
            asm volatile("cp.async.wait_group 0;" ::: "memory");
        }
        __syncthreads();

        const float* wbuf = ws_frag + cur * WS_N;
        const int xbase = cur * XS_N;

        #pragma unroll
        for (int step = 0; step < 9; step++) {
            float4 a[4];
            #pragma unroll
            for (int i = 0; i < 4; i++)
                a[i] = *reinterpret_cast<const float4*>(
                    wbuf + (((step * 4 + i) * 32 + lane) << 2));
            #pragma unroll
            for (int j = 0; j < 8; j++) {
                uint32_t b0 = xsu[xbase + boff[step][0] + j * 8];
                uint32_t b1 = xsu[xbase + boff[step][1] + j * 8];
                #pragma unroll
                for (int i = 0; i < 4; i++) {
                    asm volatile(
                        "mma.sync.aligned.m16n8k8.row.col.f32.tf32.tf32.f32 "
                        "{%0,%1,%2,%3}, {%4,%5,%6,%7}, {%8,%9}, {%0,%1,%2,%3};"
                        : "+f"(acc[i][j][0]), "+f"(acc[i][j][1]),
                          "+f"(acc[i][j][2]), "+f"(acc[i][j][3])
                        : "r"(__float_as_uint(a[i].x)), "r"(__float_as_uint(a[i].y)),
                          "r"(__float_as_uint(a[i].z)), "r"(__float_as_uint(a[i].w)),
                          "r"(b0), "r"(b1));
                }
            }
        }
        __syncthreads();   // protect buffer re-staged next iteration
    }

    // ---- epilogue: bias + float2 stores (warp = its output row) ----
    const int y   = y0 + wrp;
    const int co0 = cob * 64;
    #pragma unroll
    for (int i = 0; i < 4; i++) {
        int co_a = co0 + i * 16 + g;
        int co_b = co_a + 8;
        float bba = g_aggb[b * C + co_a];
        float bbb = g_aggb[b * C + co_b];
        #pragma unroll
        for (int j = 0; j < 8; j++) {
            int col = j * 8 + 2 * tg;
            float* pa = out + (((size_t)b * C + co_a) * Hh + y) * Ww + col;
            float* pb = out + (((size_t)b * C + co_b) * Hh + y) * Ww + col;
            *reinterpret_cast<float2*>(pa) =
                make_float2(acc[i][j][0] + bba, acc[i][j][1] + bba);
            *reinterpret_cast<float2*>(pb) =
                make_float2(acc[i][j][2] + bbb, acc[i][j][3] + bbb);
        }
    }
}

// ---------------------------------------------------------------------------
extern "C" void kernel_launch(void* const* d_in, const int* in_sizes, int n_in,
                              void* d_out, int out_size) {
    (void)in_sizes; (void)n_in; (void)out_size;
    const float* x      = (const float*)d_in[0];
    const float* weight = (const float*)d_in[1];
    const float* bias   = (const float*)d_in[2];
    const float* rw     = (const float*)d_in[3];
    const float* rb     = (const float*)d_in[4];
    float* out          = (float*)d_out;

    cudaFuncSetAttribute(conv_mma_kernel,
                         cudaFuncAttributeMaxDynamicSharedMemorySize, SMEM_BYTES);

    pool_kernel<<<B * C, 256>>>(x);
    routing_kernel<<<1, 256>>>(rw, rb, bias);
    aggw_kernel<<<(WN + 255) / 256, 256>>>(weight);
    xcvt_kernel<<<(B * C * HW / 4) / 256, 256>>>(x);

    float* xcvt_dev = nullptr;
    cudaGetSymbolAddress((void**)&xcvt_dev, g_xcvt);
    conv_mma_kernel<<<dim3(Hh / 4, C / 64, B), 128, SMEM_BYTES>>>(xcvt_dev, out);
}

// round 16
// speedup vs baseline: 8.4106x; 1.6019x over previous
#include <cuda_runtime.h>
#include <cuda_fp16.h>
#include <math.h>
#include <stdint.h>

// Problem constants
#define B   16
#define C   256     // Cin == Cout
#define Hh  64
#define Ww  64
#define E   8
#define HW  (Hh * Ww)          // 4096
#define WN  (C * C * 9)        // per-expert weight elements = 589824
#define AWU 294912             // per-b packed A uint32s: 4*16*9*4*32*4

// Scratch (allocation-free rule: __device__ globals)
__device__ float    g_pooled[B * C];
__device__ float    g_routing[B * E];
__device__ float    g_aggb[B * C];
__device__ uint32_t g_aggwh[B * AWU];     // f16x2 fragment-major weights (18.9MB)
__device__ __half   g_xh[B * HW * C];     // x in HWC f16 [b][y][x][ci] (33.5MB)

// ---- helpers --------------------------------------------------------------
__device__ __forceinline__ uint32_t smem_u32(const void* p) {
    return (uint32_t)__cvta_generic_to_shared(p);
}
#define CPA16(dst_u32, src_ptr) \
    asm volatile("cp.async.cg.shared.global [%0], [%1], 16;" \
                 :: "r"(dst_u32), "l"(src_ptr) : "memory")

// ---------------------------------------------------------------------------
// Kernel 1: global average pool.  One block per (b, ci).
// ---------------------------------------------------------------------------
__global__ void pool_kernel(const float* __restrict__ x) {
    int blk = blockIdx.x;
    const float* p = x + (size_t)blk * HW;
    float s = 0.f;
    for (int i = threadIdx.x; i < HW; i += 256) s += p[i];
    #pragma unroll
    for (int o = 16; o; o >>= 1) s += __shfl_xor_sync(0xFFFFFFFFu, s, o);
    __shared__ float wsum[8];
    if ((threadIdx.x & 31) == 0) wsum[threadIdx.x >> 5] = s;
    __syncthreads();
    if (threadIdx.x == 0) {
        float t = 0.f;
        #pragma unroll
        for (int w = 0; w < 8; w++) t += wsum[w];
        g_pooled[blk] = t * (1.0f / HW);
    }
}

// ---------------------------------------------------------------------------
// Kernel 2: routing (sigmoid) + aggregated bias.  One block.
// ---------------------------------------------------------------------------
__global__ void routing_kernel(const float* __restrict__ rw,
                               const float* __restrict__ rb,
                               const float* __restrict__ bias) {
    __shared__ float rt[B * E];
    int t = threadIdx.x;
    if (t < B * E) {
        int b = t / E, e = t % E;
        float acc = rb[e];
        const float* pp = g_pooled + b * C;
        const float* ww = rw + e * C;
        for (int c = 0; c < C; c++) acc += pp[c] * ww[c];
        float r = 1.0f / (1.0f + expf(-acc));
        rt[t] = r;
        g_routing[t] = r;
    }
    __syncthreads();
    int co = t;
    float be[E];
    #pragma unroll
    for (int e = 0; e < E; e++) be[e] = bias[e * C + co];
    #pragma unroll
    for (int b = 0; b < B; b++) {
        float a = 0.f;
        #pragma unroll
        for (int e = 0; e < E; e++) a += rt[b * E + e] * be[e];
        g_aggb[b * C + co] = a;
    }
}

// ---------------------------------------------------------------------------
// Kernel 3: weight aggregation -> f16x2 packed, m16n8k16 FRAGMENT-MAJOR.
// Per b: [cob(4)][chunk(16)][step(9)][i(4)][lane(32)][reg(4)] uint32.
//   g = lane>>2, tig = lane&3
//   co = cob*64 + i*16 + (reg&1)*8 + g
//   kl = 2*tig + (reg>>1)*8        (channel pair kl, kl+1)
//   ci = chunk*16 + kl ; tap = step
// Packed: low half = ci (even k), high half = ci+1.
// ---------------------------------------------------------------------------
__global__ void aggw_kernel(const float* __restrict__ weight) {
    __shared__ float rt[B * E];
    if (threadIdx.x < B * E) rt[threadIdx.x] = g_routing[threadIdx.x];
    __syncthreads();
    int idx = blockIdx.x * blockDim.x + threadIdx.x;
    if (idx >= AWU) return;

    int reg  = idx & 3;
    int t1   = idx >> 2;
    int lane = t1 & 31;
    int t2   = t1 >> 5;
    int i    = t2 & 3;
    int t3   = t2 >> 2;
    int step = t3 % 9;
    int t4   = t3 / 9;
    int chunk = t4 & 15;
    int cob   = t4 >> 4;
    int g   = lane >> 2;
    int tig = lane & 3;
    int co = cob * 64 + i * 16 + (reg & 1) * 8 + g;
    int kl = 2 * tig + (reg >> 1) * 8;
    int ci = chunk * 16 + kl;
    size_t src0 = ((size_t)co * C + ci) * 9 + step;   // tap = step
    size_t src1 = src0 + 9;                            // ci+1

    float w0[E], w1[E];
    #pragma unroll
    for (int e = 0; e < E; e++) {
        w0[e] = weight[(size_t)e * WN + src0];
        w1[e] = weight[(size_t)e * WN + src1];
    }
    #pragma unroll
    for (int b = 0; b < B; b++) {
        float a0 = 0.f, a1 = 0.f;
        #pragma unroll
        for (int e = 0; e < E; e++) {
            float r = rt[b * E + e];
            a0 += r * w0[e];
            a1 += r * w1[e];
        }
        __half2 h2 = __floats2half2_rn(a0, a1);
        g_aggwh[(size_t)b * AWU + idx] = *reinterpret_cast<uint32_t*>(&h2);
    }
}

// ---------------------------------------------------------------------------
// Kernel 3b: x CHW f32 -> HWC f16.  g_xh[b][y][xc][ci].
// ---------------------------------------------------------------------------
__global__ void xh_kernel(const float* __restrict__ x) {
    __shared__ float tile[32][65];
    int y = blockIdx.x, cig = blockIdx.y, b = blockIdx.z;
    int t = threadIdx.x;
    int ci0 = cig * 32;
    {
        int cl = t >> 6;       // 0..3
        int xc = t & 63;
        #pragma unroll
        for (int p = 0; p < 8; p++)
            tile[cl + p * 4][xc] =
                x[(((size_t)b * C + ci0 + cl + p * 4) * Hh + y) * Ww + xc];
    }
    __syncthreads();
    {
        int lane = t & 31;     // ci_l
        int xq   = t >> 5;     // 0..7
        #pragma unroll
        for (int p = 0; p < 8; p++) {
            int xc = xq + p * 8;
            g_xh[((((size_t)b * Hh + y) * Ww) + xc) * C + ci0 + lane] =
                __float2half_rn(tile[lane][xc]);
        }
    }
}

// ---------------------------------------------------------------------------
// Kernel 4: f16 mma.sync m16n8k16 implicit-GEMM conv (3x3, pad 1).
// Block tile M=64 couts, N=256 px (4 rows x 64); K = 16 chunks x (9 taps x 16 ch).
// 128 threads = 4 warps; warp w = output row w: 8 n-tiles x 4 m-tiles
// = 32 k16-MMAs per step; 9 steps (taps) per chunk; 16 chunks.
// smem (bytes): xs buf = [6 rows][68 cols][16 ch f16] = 13056; ws buf = 18432.
//   layout: [ xs0 | xs1 | ws0 | ws1 ] = 62976 B, double buffered cp.async.
// ---------------------------------------------------------------------------
#define XS_B  (6 * 68 * 32)      // 13056 bytes per x buffer
#define WS_B  (9 * 4 * 32 * 16)  // 18432 bytes per w buffer
#define SMEM_BYTES (2 * (XS_B + WS_B))   // 62976

__global__ __launch_bounds__(128)
void conv_mma_kernel(float* __restrict__ out) {
    extern __shared__ __align__(16) char dsm[];
    const int xs_off[2] = {0, XS_B};
    const int ws_off[2] = {2 * XS_B, 2 * XS_B + WS_B};

    const int b    = blockIdx.z;
    const int cob  = blockIdx.y;           // co block 0..3
    const int y0   = blockIdx.x * 4;
    const int tid  = threadIdx.x;
    const int wrp  = tid >> 5;             // warp = output row (0..3)
    const int lane = tid & 31;
    const int g    = lane >> 2;
    const int tg   = lane & 3;

    float acc[4][8][4];
    #pragma unroll
    for (int i = 0; i < 4; i++)
        #pragma unroll
        for (int j = 0; j < 8; j++)
            #pragma unroll
            for (int c = 0; c < 4; c++) acc[i][j][c] = 0.f;

    // B byte offsets within one xs buffer (j=0): step -> (r,s)
    int boff[9];
    #pragma unroll
    for (int step = 0; step < 9; step++) {
        int r = step / 3, s = step - r * 3;
        boff[step] = ((wrp + r) * 68 + (g + s)) * 32 + 4 * tg;
    }

    const uint32_t sb = smem_u32(dsm);

    // halo columns (col 0 and 65) zero in both buffers: 48 float4 stores
    if (tid < 48) {
        int unit = tid & 1;
        int csel = (tid >> 1) & 1;
        int row  = (tid >> 2) % 6;
        int bf   = tid / 24;
        int addr = xs_off[bf] + (row * 68 + (csel ? 65 : 0)) * 32 + unit * 16;
        *reinterpret_cast<float4*>(dsm + addr) = make_float4(0.f, 0.f, 0.f, 0.f);
    }

    const uint32_t* wsrc_base = g_aggwh + (size_t)b * AWU + (size_t)cob * (16 * 4608);
    const __half* xsrc_base = g_xh + ((size_t)b * HW) * C;

    // ---- staging (cp.async into buffer bf for chunk) ----
    auto stage = [&](int chunk, int bf) {
        const uint32_t* wsrc = wsrc_base + chunk * 4608;
        const uint32_t wdst = sb + ws_off[bf];
        #pragma unroll
        for (int t = tid; t < 1152; t += 128)
            CPA16(wdst + t * 16, wsrc + t * 4);
        const uint32_t xdst = sb + xs_off[bf];
        #pragma unroll
        for (int t = tid; t < 768; t += 128) {
            int p    = t >> 1;             // pixel 0..383
            int hlf  = t & 1;
            int row  = p >> 6;             // 0..5
            int ci_c = p & 63;             // gx
            int gy   = y0 + row - 1;
            int daddr = (row * 68 + (ci_c + 1)) * 32 + hlf * 16;
            if ((unsigned)gy < (unsigned)Hh) {
                const __half* src =
                    xsrc_base + ((size_t)gy * Ww + ci_c) * C + chunk * 16 + hlf * 8;
                CPA16(xdst + daddr, src);
            } else {
                *reinterpret_cast<float4*>(dsm + xs_off[bf] + daddr) =
                    make_float4(0.f, 0.f, 0.f, 0.f);
            }
        }
        asm volatile("cp.async.commit_group;" ::: "memory");
    };

    // ---- prologue ----
    stage(0, 0);

    for (int chunk = 0; chunk < 16; chunk++) {
        const int cur = chunk & 1;
        if (chunk + 1 < 16) {
            stage(chunk + 1, cur ^ 1);
            asm volatile("cp.async.wait_group 1;" ::: "memory");
        } else {
            asm volatile("cp.async.wait_group 0;" ::: "memory");
        }
        __syncthreads();

        const char* wbuf = dsm + ws_off[cur];
        const char* xbuf = dsm + xs_off[cur];

        #pragma unroll
        for (int step = 0; step < 9; step++) {
            uint4 a[4];
            #pragma unroll
            for (int i = 0; i < 4; i++)
                a[i] = *reinterpret_cast<const uint4*>(
                    wbuf + ((step * 4 + i) * 32 + lane) * 16);
            #pragma unroll
            for (int j = 0; j < 8; j++) {
                uint32_t b0 = *reinterpret_cast<const uint32_t*>(
                    xbuf + boff[step] + j * 256);
                uint32_t b1 = *reinterpret_cast<const uint32_t*>(
                    xbuf + boff[step] + j * 256 + 16);
                #pragma unroll
                for (int i = 0; i < 4; i++) {
                    asm volatile(
                        "mma.sync.aligned.m16n8k16.row.col.f32.f16.f16.f32 "
                        "{%0,%1,%2,%3}, {%4,%5,%6,%7}, {%8,%9}, {%0,%1,%2,%3};"
                        : "+f"(acc[i][j][0]), "+f"(acc[i][j][1]),
                          "+f"(acc[i][j][2]), "+f"(acc[i][j][3])
                        : "r"(a[i].x), "r"(a[i].y), "r"(a[i].z), "r"(a[i].w),
                          "r"(b0), "r"(b1));
                }
            }
        }
        __syncthreads();   // protect buffer re-staged next iteration
    }

    // ---- epilogue: bias + float2 stores (warp = its output row) ----
    const int y   = y0 + wrp;
    const int co0 = cob * 64;
    float* outb = out + (size_t)b * C * HW;
    #pragma unroll
    for (int i = 0; i < 4; i++) {
        int co_a = co0 + i * 16 + g;
        int co_b = co_a + 8;
        float bba = g_aggb[b * C + co_a];
        float bbb = g_aggb[b * C + co_b];
        #pragma unroll
        for (int j = 0; j < 8; j++) {
            int col = j * 8 + 2 * tg;
            float* pa = outb + ((size_t)co_a * Hh + y) * Ww + col;
            float* pb = outb + ((size_t)co_b * Hh + y) * Ww + col;
            *reinterpret_cast<float2*>(pa) =
                make_float2(acc[i][j][0] + bba, acc[i][j][1] + bba);
            *reinterpret_cast<float2*>(pb) =
                make_float2(acc[i][j][2] + bbb, acc[i][j][3] + bbb);
        }
    }
}

// ---------------------------------------------------------------------------
extern "C" void kernel_launch(void* const* d_in, const int* in_sizes, int n_in,
                              void* d_out, int out_size) {
    (void)in_sizes; (void)n_in; (void)out_size;
    const float* x      = (const float*)d_in[0];
    const float* weight = (const float*)d_in[1];
    const float* bias   = (const float*)d_in[2];
    const float* rw     = (const float*)d_in[3];
    const float* rb     = (const float*)d_in[4];
    float* out          = (float*)d_out;

    cudaFuncSetAttribute(conv_mma_kernel,
                         cudaFuncAttributeMaxDynamicSharedMemorySize, SMEM_BYTES);

    pool_kernel<<<B * C, 256>>>(x);
    routing_kernel<<<1, 256>>>(rw, rb, bias);
    aggw_kernel<<<(AWU + 255) / 256, 256>>>(weight);
    xh_kernel<<<dim3(Hh, 8, B), 256>>>(x);

    conv_mma_kernel<<<dim3(Hh / 4, C / 64, B), 128, SMEM_BYTES>>>(out);
}